// round 6
// baseline (speedup 1.0000x reference)
#include <cuda_runtime.h>
#include <cstdint>

// x: (B=8, C=16, T=2000, F=128) fp32. Per (b,c,f) column: POOL=10 block sums,
// causal cumulative mean/var over pooled blocks, normalize. Single pass.
//
// Grid = 512 CTAs: (b*C+c) x (f-quarter of 32). 128 threads/CTA, ~3.5 CTA/SM
// so all 148 SMs stay busy and one CTA's barriers overlap another's memory.
// Ring of NS=4 tiles (TB=8 pooled blocks x 32 f = 10240 B) loaded with
// cp.async.128 (16 B/thread): ~15 outstanding reqs/warp (under the ~55 LSU
// cap), ~15 MB chip-wide in flight. Per tile: parallel block sums -> 8-step
// serial cumsum on warp 0 -> float4 normalize + coalesced STG.128.

#define TT      2000
#define FF      128
#define PP      10
#define TT1     200
#define TB      8                    // pooled blocks per tile
#define NT      25                   // tiles
#define NS      4                    // ring stages
#define QF      32                   // f-columns per CTA
#define ROWS    (TB * PP)            // 80 rows per tile
#define TILE_F  (ROWS * QF)          // 2560 floats
#define TILE_B  (TILE_F * 4)         // 10240 bytes
#define ROW_B   (FF * 4)             // 512-byte global row stride
#define EPSV    1e-5f

__device__ __forceinline__ uint32_t s2u32(const void* p) {
    uint32_t a;
    asm("{ .reg .u64 t; cvta.to.shared.u64 t, %1; cvt.u32.u64 %0, t; }"
        : "=r"(a) : "l"(p));
    return a;
}
__device__ __forceinline__ void cp16(uint32_t saddr, const void* gaddr) {
    asm volatile("cp.async.cg.shared.global [%0], [%1], 16;\n"
                 :: "r"(saddr), "l"(gaddr));
}
#define CP_COMMIT() asm volatile("cp.async.commit_group;\n")
#define CP_WAIT(n)  asm volatile("cp.async.wait_group %0;\n" :: "n"(n))

__global__ void __launch_bounds__(128)
inorm_kernel(const float* __restrict__ x, float* __restrict__ out)
{
    __shared__ float4 ring4[NS * TILE_F / 4];   // 40960 B
    __shared__ float2 bsArr[TB * QF];           //  2048 B
    __shared__ float  mArr[TB * QF];            //  1024 B
    __shared__ float  rArr[TB * QF];            //  1024 B

    const int col = blockIdx.x >> 2;            // 0..127
    const int q   = blockIdx.x & 3;             // f-quarter
    const int tid = threadIdx.x;

    const char* gq = (const char*)(x   + (size_t)col * (TT * FF) + q * QF);
    char*       oq = (char*)(out + (size_t)col * (TT * FF) + q * QF);

    const uint32_t sring = s2u32(ring4);

    // Prologue: fill ring with tiles 0..NS-1 (one commit group per stage/warp)
    #pragma unroll
    for (int st = 0; st < NS; st++) {
        #pragma unroll
        for (int i = 0; i < 5; i++) {
            const int j  = tid + 128 * i;       // 0..639 float4 slots
            const int r  = j >> 3;
            const int c4 = j & 7;
            cp16(sring + st * TILE_B + j * 16,
                 gq + (size_t)(st * ROWS + r) * ROW_B + c4 * 16);
        }
        CP_COMMIT();
    }

    float sAcc = 0.f, s2Acc = 0.f;              // live in warp 0 only
    int st = 0;

    #pragma unroll 1
    for (int t = 0; t < NT; t++) {
        // My copies into stage st are done; barrier extends that to all warps.
        CP_WAIT(NS - 1);
        __syncthreads();

        const float* tile = (const float*)ring4 + st * TILE_F;

        // ── A: parallel block sums. thread -> (b = tid>>5 (+4), f = tid&31)
        {
            const int f = tid & 31;
            #pragma unroll
            for (int bb = 0; bb < 2; bb++) {
                const int b = (tid >> 5) + bb * 4;
                const float* rp = tile + b * (PP * QF) + f;
                float bs = 0.f, bs2 = 0.f;
                #pragma unroll
                for (int i = 0; i < PP; i++) {
                    const float a = rp[i * QF];
                    bs += a; bs2 = fmaf(a, a, bs2);
                }
                bsArr[b * QF + f] = make_float2(bs, bs2);
            }
        }
        __syncthreads();

        // ── B: tiny serial cumsum over TB blocks (warp 0, lane = f)
        if (tid < 32) {
            #pragma unroll
            for (int b = 0; b < TB; b++) {
                const float2 v = bsArr[b * QF + tid];
                sAcc += v.x; s2Acc += v.y;
                const float invn = __fdividef(1.0f, (float)((t * TB + b + 1) * PP));
                const float m    = sAcc * invn;
                const float var  = fmaf(-m, m, s2Acc * invn);
                mArr[b * QF + tid] = m;
                rArr[b * QF + tid] = rsqrtf(var + EPSV);
            }
        }
        __syncthreads();

        // ── C: parallel normalize, 5 float4/thread, coalesced STG.128
        {
            const float4* tile4 = (const float4*)tile;
            const float4* m4    = (const float4*)mArr;
            const float4* r4    = (const float4*)rArr;
            #pragma unroll
            for (int i = 0; i < 5; i++) {
                const int j  = tid + 128 * i;
                const int r  = j >> 3;
                const int b  = r / PP;
                const int c4 = j & 7;
                const float4 xv = tile4[j];
                const float4 mv = m4[b * 8 + c4];
                const float4 rv = r4[b * 8 + c4];
                float4 res;
                res.x = (xv.x - mv.x) * rv.x;
                res.y = (xv.y - mv.y) * rv.y;
                res.z = (xv.z - mv.z) * rv.z;
                res.w = (xv.w - mv.w) * rv.w;
                *(float4*)(oq + (size_t)(t * ROWS + r) * ROW_B + c4 * 16) = res;
            }
        }
        __syncthreads();   // all reads of stage st complete

        // ── refill stage st with tile t+NS (uniform branch; always commit)
        const int tn = t + NS;
        if (tn < NT) {
            #pragma unroll
            for (int i = 0; i < 5; i++) {
                const int j  = tid + 128 * i;
                const int r  = j >> 3;
                const int c4 = j & 7;
                cp16(sring + st * TILE_B + j * 16,
                     gq + (size_t)(tn * ROWS + r) * ROW_B + c4 * 16);
            }
        }
        CP_COMMIT();

        if (++st == NS) st = 0;
    }
}

extern "C" void kernel_launch(void* const* d_in, const int* in_sizes, int n_in,
                              void* d_out, int out_size)
{
    const float* x   = (const float*)d_in[0];
    float*       out = (float*)d_out;
    inorm_kernel<<<512, 128>>>(x, out);
}

// round 8
// speedup vs baseline: 1.0679x; 1.0679x over previous
#include <cuda_runtime.h>
#include <cstdint>

// x: (B=8, C=16, T=2000, F=128) fp32. Per (b,c,f) column: POOL=10 block sums,
// causal cumulative mean/var over pooled blocks, normalize. Single pass.
//
// Grid = 1024 CTAs: (b*C+c) x (f-group of 16). 128 threads/CTA -> ~28 warps/SM
// so CP_WAIT/barrier bubbles in one CTA hide behind co-resident CTAs.
// Ring of NS=5 tiles (TB=8 pooled blocks x 16 f = 5120 B = 320 float4 slots).
// All tile loops run 3 guarded iterations over the 320 slots (R7 bug: ran 10
// unguarded iterations -> 4x smem overrun -> illegal access).

#define TT      2000
#define FF      128
#define PP      10
#define TT1     200
#define TB      8                    // pooled blocks per tile
#define NT      25                   // tiles
#define NS      5                    // ring stages
#define QF      16                   // f-columns per CTA
#define ROWS    (TB * PP)            // 80 rows per tile
#define TILE_F  (ROWS * QF)          // 1280 floats
#define TILE_B  (TILE_F * 4)         // 5120 bytes
#define SLOTS4  (TILE_F / 4)         // 320 float4 slots
#define ROW_B   (FF * 4)             // 512-byte global row stride
#define EPSV    1e-5f

__device__ __forceinline__ uint32_t s2u32(const void* p) {
    uint32_t a;
    asm("{ .reg .u64 t; cvta.to.shared.u64 t, %1; cvt.u32.u64 %0, t; }"
        : "=r"(a) : "l"(p));
    return a;
}
__device__ __forceinline__ void cp16(uint32_t saddr, const void* gaddr) {
    asm volatile("cp.async.cg.shared.global [%0], [%1], 16;\n"
                 :: "r"(saddr), "l"(gaddr));
}
#define CP_COMMIT() asm volatile("cp.async.commit_group;\n")
#define CP_WAIT(n)  asm volatile("cp.async.wait_group %0;\n" :: "n"(n))

__global__ void __launch_bounds__(128)
inorm_kernel(const float* __restrict__ x, float* __restrict__ out)
{
    __shared__ float4 ring4[NS * SLOTS4];       // 25600 B
    __shared__ float2 bsArr[TB * QF];           //  1024 B
    __shared__ float  mArr[TB * QF];            //   512 B
    __shared__ float  rArr[TB * QF];            //   512 B

    const int col = blockIdx.x >> 3;            // 0..127
    const int q   = blockIdx.x & 7;             // f-group of 16
    const int tid = threadIdx.x;

    const char* gq = (const char*)(x   + (size_t)col * (TT * FF) + q * QF);
    char*       oq = (char*)(out + (size_t)col * (TT * FF) + q * QF);

    const uint32_t sring = s2u32(ring4);

    // Prologue: fill ring with tiles 0..NS-1 (one commit group per stage)
    #pragma unroll
    for (int st = 0; st < NS; st++) {
        #pragma unroll
        for (int i = 0; i < 3; i++) {
            const int j = tid + 128 * i;        // float4 slot
            if (j < SLOTS4) {
                const int r  = j >> 2;          // row 0..79
                const int c4 = j & 3;           // float4 within 64B row seg
                cp16(sring + st * TILE_B + j * 16,
                     gq + (size_t)(st * ROWS + r) * ROW_B + c4 * 16);
            }
        }
        CP_COMMIT();
    }

    float sAcc = 0.f, s2Acc = 0.f;              // live in warp 0 lanes 0..15
    int st = 0;

    #pragma unroll 1
    for (int t = 0; t < NT; t++) {
        CP_WAIT(NS - 1);
        __syncthreads();

        const float* tile = (const float*)ring4 + st * TILE_F;

        // ── A: parallel block sums. thread -> (b = tid>>4, f = tid&15)
        {
            const int b = tid >> 4;             // 0..7
            const int f = tid & 15;
            const float* rp = tile + b * (PP * QF) + f;
            float bs = 0.f, bs2 = 0.f;
            #pragma unroll
            for (int i = 0; i < PP; i++) {
                const float a = rp[i * QF];
                bs += a; bs2 = fmaf(a, a, bs2);
            }
            bsArr[b * QF + f] = make_float2(bs, bs2);
        }
        __syncthreads();

        // ── B: tiny serial cumsum over TB blocks (warp 0, lanes 0..15 = f)
        if (tid < QF) {
            #pragma unroll
            for (int b = 0; b < TB; b++) {
                const float2 v = bsArr[b * QF + tid];
                sAcc += v.x; s2Acc += v.y;
                const float invn = __fdividef(1.0f, (float)((t * TB + b + 1) * PP));
                const float m    = sAcc * invn;
                const float var  = fmaf(-m, m, s2Acc * invn);
                mArr[b * QF + tid] = m;
                rArr[b * QF + tid] = rsqrtf(var + EPSV);
            }
        }
        __syncthreads();

        // ── C: parallel normalize over 320 float4 slots, coalesced STG.128
        {
            const float4* tile4 = (const float4*)tile;
            const float4* m4    = (const float4*)mArr;
            const float4* r4    = (const float4*)rArr;
            #pragma unroll
            for (int i = 0; i < 3; i++) {
                const int j = tid + 128 * i;
                if (j < SLOTS4) {
                    const int r  = j >> 2;
                    const int b  = r / PP;
                    const int c4 = j & 3;
                    const float4 xv = tile4[j];
                    const float4 mv = m4[b * 4 + c4];
                    const float4 rv = r4[b * 4 + c4];
                    float4 res;
                    res.x = (xv.x - mv.x) * rv.x;
                    res.y = (xv.y - mv.y) * rv.y;
                    res.z = (xv.z - mv.z) * rv.z;
                    res.w = (xv.w - mv.w) * rv.w;
                    *(float4*)(oq + (size_t)(t * ROWS + r) * ROW_B + c4 * 16) = res;
                }
            }
        }
        __syncthreads();   // all reads of stage st complete

        // ── refill stage st with tile t+NS (uniform branch; always commit)
        const int tn = t + NS;
        if (tn < NT) {
            #pragma unroll
            for (int i = 0; i < 3; i++) {
                const int j = tid + 128 * i;
                if (j < SLOTS4) {
                    const int r  = j >> 2;
                    const int c4 = j & 3;
                    cp16(sring + st * TILE_B + j * 16,
                         gq + (size_t)(tn * ROWS + r) * ROW_B + c4 * 16);
                }
            }
        }
        CP_COMMIT();

        if (++st == NS) st = 0;
    }
}

extern "C" void kernel_launch(void* const* d_in, const int* in_sizes, int n_in,
                              void* d_out, int out_size)
{
    const float* x   = (const float*)d_in[0];
    float*       out = (float*)d_out;
    inorm_kernel<<<1024, 128>>>(x, out);
}